// round 12
// baseline (speedup 1.0000x reference)
#include <cuda_runtime.h>
#include <math.h>

#define T_MAX 16384
#define SDIM 2048
#define MDIM 16

// ---- device scratch (no allocations allowed) ----
__device__ float g_em[T_MAX * SDIM];       // exp(em[t,s] - rowmax[t])  (128 MB)
__device__ float g_mx[T_MAX];              // rowmax[t]
__device__ float g_loglamT[MDIM * SDIM];   // log(lam_c) transposed: [m][s]
__device__ float g_lamsum[SDIM];
__device__ float g_pi[SDIM];               // exp(combined logpi)

// ---- f32x2 packed-FMA helpers (sm_103a) ----
__device__ __forceinline__ unsigned long long fma2(unsigned long long a,
                                                   unsigned long long b,
                                                   unsigned long long c) {
    unsigned long long d;
    asm("fma.rn.f32x2 %0, %1, %2, %3;" : "=l"(d) : "l"(a), "l"(b), "l"(c));
    return d;
}
__device__ __forceinline__ unsigned long long mul2(unsigned long long a,
                                                   unsigned long long b) {
    unsigned long long d;
    asm("mul.rn.f32x2 %0, %1, %2;" : "=l"(d) : "l"(a), "l"(b));
    return d;
}
__device__ __forceinline__ float hadd2(unsigned long long v) {
    float lo, hi;
    asm("mov.b64 {%0, %1}, %2;" : "=f"(lo), "=f"(hi) : "l"(v));
    return lo + hi;
}

// ============================================================
// Kernel 1: combined rates, log-rates (transposed), priors
// ============================================================
__global__ void setup_kernel(const float* __restrict__ lam1,
                             const float* __restrict__ lam2,
                             const float* __restrict__ lam3,
                             const float* __restrict__ logpi1,
                             const float* __restrict__ logpi2,
                             const float* __restrict__ logpi3) {
    int s = blockIdx.x * blockDim.x + threadIdx.x;
    if (s >= SDIM) return;
    int s1 = s >> 7, s2 = (s >> 3) & 15, s3 = s & 7;
    float lsum = 0.f;
#pragma unroll
    for (int m = 0; m < MDIM; m++) {
        float lam = lam1[s1 * MDIM + m] + lam2[s2 * MDIM + m] + lam3[s3 * MDIM + m];
        lsum += lam;
        g_loglamT[m * SDIM + s] = logf(lam);
    }
    g_lamsum[s] = lsum;
    g_pi[s] = expf(logpi1[s1] + logpi2[s2] + logpi3[s3]);
}

// ============================================================
// Kernel 2: per-timestep emissions, normalized to exp(em - max)
// ============================================================
__global__ void emis_kernel(const int* __restrict__ x) {
    int t = blockIdx.x;
    int tid = threadIdx.x;
    __shared__ float xf[MDIM];
    __shared__ float red[8];

    if (tid < MDIM) xf[tid] = (float)x[t * MDIM + tid];
    __syncthreads();

    float lg = 0.f;
#pragma unroll
    for (int m = 0; m < MDIM; m++) lg += lgammaf(xf[m] + 1.0f);

    float e[8];
#pragma unroll
    for (int j = 0; j < 8; j++) e[j] = 0.f;

#pragma unroll
    for (int m = 0; m < MDIM; m++) {
        float xm = xf[m];
        const float* row = &g_loglamT[m * SDIM];
#pragma unroll
        for (int j = 0; j < 8; j++) e[j] = fmaf(xm, row[tid + j * 256], e[j]);
    }
#pragma unroll
    for (int j = 0; j < 8; j++) e[j] = e[j] - g_lamsum[tid + j * 256] - lg;

    float mloc = -3.4e38f;
#pragma unroll
    for (int j = 0; j < 8; j++) mloc = fmaxf(mloc, e[j]);
#pragma unroll
    for (int o = 16; o > 0; o >>= 1)
        mloc = fmaxf(mloc, __shfl_xor_sync(0xffffffffu, mloc, o));
    if ((tid & 31) == 0) red[tid >> 5] = mloc;
    __syncthreads();
    float mx = red[0];
#pragma unroll
    for (int k = 1; k < 8; k++) mx = fmaxf(mx, red[k]);

    float* outrow = &g_em[(size_t)t * SDIM];
#pragma unroll
    for (int j = 0; j < 8; j++) outrow[tid + j * 256] = expf(e[j] - mx);
    if (tid == 0) g_mx[t] = mx;
}

// ============================================================
// Kernel 3: persistent single-CTA scaled-linear forward scan.
// 1024 threads, 2 outputs/thread (8 warps/SMSP for latency hiding).
// STABLE normalization: scale 1/S_{t-1} applied at step t; S_{t-1}
// reduced by warp0 alone from psArr (off every other warp's path).
//
// Layouts (floats):
//   aS[buf][d2*132 + d1*8 + d3]                (d2-row pad 132)
//   bS[(p1*8 + d3)*20 + p2]                    (row pad 20)
//   cS[(d2*8 + d3)*20 + (p1 ^ 4*(d2&3))]       (row pad 20, chunk-XOR swizzle)
//   A1p/A2p[row*20 + col]                      (row pad 20)
// ============================================================
__global__ void __launch_bounds__(1024, 1)
scan_kernel(const float* __restrict__ logA1,
            const float* __restrict__ logA2,
            const float* __restrict__ logA3,
            float* __restrict__ out) {
    __shared__ __align__(16) float A1p[16 * 20];
    __shared__ __align__(16) float A2p[16 * 20];
    __shared__ __align__(16) float A3s[64];
    __shared__ __align__(16) float aS[2][16 * 132];
    __shared__ __align__(16) float bS[128 * 20];
    __shared__ __align__(16) float cS[128 * 20];
    __shared__ __align__(16) float psArr[1024];
    __shared__ float SinvBuf;

    const int tid = threadIdx.x;
    const int warp = tid >> 5, lane = tid & 31;

    // exp'd, padded transition matrices
    if (tid < 256) {
        A1p[(tid >> 4) * 20 + (tid & 15)] = expf(logA1[tid]);
    } else if (tid < 512) {
        int u = tid - 256;
        A2p[(u >> 4) * 20 + (u & 15)] = expf(logA2[u]);
    } else if (tid < 576) {
        A3s[tid - 512] = expf(logA3[tid - 512]);
    }

    // ---- phase-2 ids: q=(p1,p2), sub in 0..3; outputs d3 = sub, sub+4
    const int q = tid >> 2;
    const int p2p1 = q >> 4, p2p2 = q & 15, p2sub = tid & 3;

    // ---- phase-3 ids: g3=(p1,d3), sub in 0..7; outputs d2 = sub, sub+8
    const int g3 = tid >> 3;
    const int p3p1 = g3 >> 3, p3d3 = g3 & 7, p3sub = tid & 7;
    const int p3x = 4 * (p3sub & 3);   // cS chunk-XOR (d2&3 == p3sub&3)

    // ---- phase-4 ids: g4=(d2,d3), sub in 0..7; outputs d1 = sub, sub+8
    const int g4 = tid >> 3;
    const int p4d2 = g4 >> 3, p4d3 = g4 & 7, p4sub = tid & 7;
    const int em_b = p4sub * 128 + p4d2 * 8 + p4d3;    // + k*1024 (global state idx)
    const int aw_b = p4d2 * 132 + p4sub * 8 + p4d3;    // + k*64   (smem aS idx)
    const int cvbase = (p4d2 * 8 + p4d3) * 20;
    const int sxor = p4d2 & 3;

    double Lmx = 0.0, Lls = 0.0;
    float mx_reg = g_mx[0];

    __syncthreads();

    // ---- t = 0: w = em0 * pi
    {
        float ps = 0.f;
#pragma unroll
        for (int k = 0; k < 2; k++) {
            int ei = em_b + k * 1024;
            float u = g_em[ei] * g_pi[ei];
            aS[0][aw_b + k * 64] = u;
            ps += u;
        }
        psArr[tid] = ps;
    }
    __syncthreads();

    for (int t = 1; t < T_MAX; t++) {
        const float* acur = &aS[(t - 1) & 1][0];
        float* anext = &aS[t & 1][0];

        // ---- warp0: reduce psArr -> S_{t-1}; overlaps phases 2-3 of the
        //      other 31 warps (SinvBuf consumed only in phase 4).
        if (warp == 0) {
            const float4* pp = (const float4*)psArr;
            float r = 0.f;
#pragma unroll
            for (int j = 0; j < 8; j++) {
                float4 v = pp[lane + j * 32];
                r += (v.x + v.y) + (v.z + v.w);
            }
#pragma unroll
            for (int o = 16; o > 0; o >>= 1) r += __shfl_xor_sync(0xffffffffu, r, o);
            if (lane == 0) {
                SinvBuf = 1.0f / r;
                Lls += (double)logf(r);      // log S_{t-1}
                Lmx += (double)mx_reg;       // mx_{t-1}
                mx_reg = g_mx[t];
            }
        }

        // prefetch emissions (consumed in phase 4)
        const float* emt = g_em + (size_t)t * SDIM + em_b;
        float eg0 = emt[0], eg1 = emt[1024];

        // ---- phase 2: b[p1,d3,p2] = sum_p3 A3[d3,p3] * a[p2,p1,p3]
        {
            const float* ap = acur + p2p2 * 132 + p2p1 * 8;
            ulonglong2 V0 = *(const ulonglong2*)ap;
            ulonglong2 V1 = *(const ulonglong2*)(ap + 4);
#pragma unroll
            for (int k = 0; k < 2; k++) {
                int d3 = p2sub + 4 * k;
                const ulonglong2* ar = (const ulonglong2*)(A3s + d3 * 8);
                ulonglong2 A0 = ar[0], A1r = ar[1];
                unsigned long long acc = mul2(A0.x, V0.x);
                acc = fma2(A0.y, V0.y, acc);
                acc = fma2(A1r.x, V1.x, acc);
                acc = fma2(A1r.y, V1.y, acc);
                bS[(p2p1 * 8 + d3) * 20 + p2p2] = hadd2(acc);
            }
        }
        __syncthreads();

        // ---- phase 3: c[p1,d2,d3] = sum_p2 A2[d2,p2] * b[p1,d3,p2]
        {
            const ulonglong2* bp = (const ulonglong2*)(bS + (p3p1 * 8 + p3d3) * 20);
            ulonglong2 B0 = bp[0], B1 = bp[1], B2 = bp[2], B3 = bp[3];
#pragma unroll
            for (int k = 0; k < 2; k++) {
                int d2 = p3sub + 8 * k;
                const ulonglong2* w = (const ulonglong2*)(A2p + d2 * 20);
                ulonglong2 Wa = w[0], Wb = w[1], Wc = w[2], Wd = w[3];
                unsigned long long acc = mul2(Wa.x, B0.x);
                acc = fma2(Wa.y, B0.y, acc);
                acc = fma2(Wb.x, B1.x, acc);
                acc = fma2(Wb.y, B1.y, acc);
                acc = fma2(Wc.x, B2.x, acc);
                acc = fma2(Wc.y, B2.y, acc);
                acc = fma2(Wd.x, B3.x, acc);
                acc = fma2(Wd.y, B3.y, acc);
                cS[(d2 * 8 + p3d3) * 20 + (p3p1 ^ p3x)] = hadd2(acc);
            }
        }
        __syncthreads();

        // ---- phase 4: w[d1,d2,d3] = em * (1/S_{t-1}) * sum_p1 A1[d1,p1]*c[p1,d2,d3]
        {
            const float* crow = cS + cvbase;
            ulonglong2 CV0 = *(const ulonglong2*)(crow + 4 * (0 ^ sxor));
            ulonglong2 CV1 = *(const ulonglong2*)(crow + 4 * (1 ^ sxor));
            ulonglong2 CV2 = *(const ulonglong2*)(crow + 4 * (2 ^ sxor));
            ulonglong2 CV3 = *(const ulonglong2*)(crow + 4 * (3 ^ sxor));
            float invS = SinvBuf;
            float ps = 0.f;
#pragma unroll
            for (int k = 0; k < 2; k++) {
                int d1 = p4sub + 8 * k;
                const ulonglong2* w = (const ulonglong2*)(A1p + d1 * 20);
                ulonglong2 Wa = w[0], Wb = w[1], Wc = w[2], Wd = w[3];
                unsigned long long acc = mul2(Wa.x, CV0.x);
                acc = fma2(Wa.y, CV0.y, acc);
                acc = fma2(Wb.x, CV1.x, acc);
                acc = fma2(Wb.y, CV1.y, acc);
                acc = fma2(Wc.x, CV2.x, acc);
                acc = fma2(Wc.y, CV2.y, acc);
                acc = fma2(Wd.x, CV3.x, acc);
                acc = fma2(Wd.y, CV3.y, acc);
                float eg = (k == 0) ? eg0 : eg1;
                float u = eg * invS * hadd2(acc);
                anext[aw_b + k * 64] = u;
                ps += u;
            }
            psArr[tid] = ps;
        }
        __syncthreads();
    }

    // ---- finalize: S_{T-1}
    if (warp == 0) {
        const float4* pp = (const float4*)psArr;
        float r = 0.f;
#pragma unroll
        for (int j = 0; j < 8; j++) {
            float4 v = pp[lane + j * 32];
            r += (v.x + v.y) + (v.z + v.w);
        }
#pragma unroll
        for (int o = 16; o > 0; o >>= 1) r += __shfl_xor_sync(0xffffffffu, r, o);
        if (lane == 0) {
            double L = Lmx + Lls + (double)mx_reg + (double)logf(r);
            out[0] = (float)L;
        }
    }
}

// ============================================================
extern "C" void kernel_launch(void* const* d_in, const int* in_sizes, int n_in,
                              void* d_out, int out_size) {
    const int*   x      = (const int*)d_in[0];
    const float* lam1   = (const float*)d_in[1];
    const float* lam2   = (const float*)d_in[2];
    const float* lam3   = (const float*)d_in[3];
    const float* logA1  = (const float*)d_in[4];
    const float* logA2  = (const float*)d_in[5];
    const float* logA3  = (const float*)d_in[6];
    const float* logpi1 = (const float*)d_in[7];
    const float* logpi2 = (const float*)d_in[8];
    const float* logpi3 = (const float*)d_in[9];
    float* out = (float*)d_out;

    setup_kernel<<<8, 256>>>(lam1, lam2, lam3, logpi1, logpi2, logpi3);
    emis_kernel<<<T_MAX, 256>>>(x);
    scan_kernel<<<1, 1024>>>(logA1, logA2, logA3, out);
}

// round 13
// speedup vs baseline: 1.7836x; 1.7836x over previous
#include <cuda_runtime.h>
#include <math.h>

#define T_MAX 16384
#define SDIM 2048
#define MDIM 16

// ---- device scratch (no allocations allowed) ----
__device__ float g_em[T_MAX * SDIM];       // exp(em[t,s] - rowmax[t])  (128 MB)
__device__ float g_mx[T_MAX];              // rowmax[t]
__device__ float g_loglamT[MDIM * SDIM];   // log(lam_c) transposed: [m][s]
__device__ float g_lamsum[SDIM];
__device__ float g_pi[SDIM];               // exp(combined logpi)

// ---- f32x2 packed-FMA helpers (sm_103a) ----
__device__ __forceinline__ unsigned long long pk2(float lo, float hi) {
    unsigned long long r;
    asm("mov.b64 %0, {%1, %2};" : "=l"(r) : "f"(lo), "f"(hi));
    return r;
}
__device__ __forceinline__ unsigned long long fma2(unsigned long long a,
                                                   unsigned long long b,
                                                   unsigned long long c) {
    unsigned long long d;
    asm("fma.rn.f32x2 %0, %1, %2, %3;" : "=l"(d) : "l"(a), "l"(b), "l"(c));
    return d;
}
__device__ __forceinline__ unsigned long long mul2(unsigned long long a,
                                                   unsigned long long b) {
    unsigned long long d;
    asm("mul.rn.f32x2 %0, %1, %2;" : "=l"(d) : "l"(a), "l"(b));
    return d;
}
__device__ __forceinline__ float hadd2(unsigned long long v) {
    float lo, hi;
    asm("mov.b64 {%0, %1}, %2;" : "=f"(lo), "=f"(hi) : "l"(v));
    return lo + hi;
}

// ============================================================
// Kernel 1: combined rates, log-rates (transposed), priors
// ============================================================
__global__ void setup_kernel(const float* __restrict__ lam1,
                             const float* __restrict__ lam2,
                             const float* __restrict__ lam3,
                             const float* __restrict__ logpi1,
                             const float* __restrict__ logpi2,
                             const float* __restrict__ logpi3) {
    int s = blockIdx.x * blockDim.x + threadIdx.x;
    if (s >= SDIM) return;
    int s1 = s >> 7, s2 = (s >> 3) & 15, s3 = s & 7;
    float lsum = 0.f;
#pragma unroll
    for (int m = 0; m < MDIM; m++) {
        float lam = lam1[s1 * MDIM + m] + lam2[s2 * MDIM + m] + lam3[s3 * MDIM + m];
        lsum += lam;
        g_loglamT[m * SDIM + s] = logf(lam);
    }
    g_lamsum[s] = lsum;
    g_pi[s] = expf(logpi1[s1] + logpi2[s2] + logpi3[s3]);
}

// ============================================================
// Kernel 2: per-timestep emissions, normalized to exp(em - max)
// ============================================================
__global__ void emis_kernel(const int* __restrict__ x) {
    int t = blockIdx.x;
    int tid = threadIdx.x;
    __shared__ float xf[MDIM];
    __shared__ float red[8];

    if (tid < MDIM) xf[tid] = (float)x[t * MDIM + tid];
    __syncthreads();

    float lg = 0.f;
#pragma unroll
    for (int m = 0; m < MDIM; m++) lg += lgammaf(xf[m] + 1.0f);

    float e[8];
#pragma unroll
    for (int j = 0; j < 8; j++) e[j] = 0.f;

#pragma unroll
    for (int m = 0; m < MDIM; m++) {
        float xm = xf[m];
        const float* row = &g_loglamT[m * SDIM];
#pragma unroll
        for (int j = 0; j < 8; j++) e[j] = fmaf(xm, row[tid + j * 256], e[j]);
    }
#pragma unroll
    for (int j = 0; j < 8; j++) e[j] = e[j] - g_lamsum[tid + j * 256] - lg;

    float mloc = -3.4e38f;
#pragma unroll
    for (int j = 0; j < 8; j++) mloc = fmaxf(mloc, e[j]);
#pragma unroll
    for (int o = 16; o > 0; o >>= 1)
        mloc = fmaxf(mloc, __shfl_xor_sync(0xffffffffu, mloc, o));
    if ((tid & 31) == 0) red[tid >> 5] = mloc;
    __syncthreads();
    float mx = red[0];
#pragma unroll
    for (int k = 1; k < 8; k++) mx = fmaxf(mx, red[k]);

    float* outrow = &g_em[(size_t)t * SDIM];
#pragma unroll
    for (int j = 0; j < 8; j++) outrow[tid + j * 256] = expf(e[j] - mx);
    if (tid == 0) g_mx[t] = mx;
}

// ============================================================
// Kernel 3: persistent single-CTA scaled-linear forward scan.
// 256 threads, 8 outputs/thread (minimize per-warp barrier overhead;
// latency covered by in-thread ILP; A3 register-resident; emissions
// prefetched one full step ahead).
//
// Layouts (floats):
//   aS[buf][d1*132 + d2*8 + d3]                          (d1-row pad 132)
//   bS[((p1>>1)*8 + d3)*36 + 16*(p1&1) + p2]             (paired-p1 rows, pad 36)
//   cS[d2*164 + d3*20 + (p1 ^ 4*(d2&3))]                 (chunk-XOR swizzle)
//   A1p/A2p[row*20 + col]                                (row pad 20)
// ============================================================
__global__ void __launch_bounds__(256, 1)
scan_kernel(const float* __restrict__ logA1,
            const float* __restrict__ logA2,
            const float* __restrict__ logA3,
            float* __restrict__ out) {
    __shared__ __align__(16) float A1p[16 * 20];
    __shared__ __align__(16) float A2p[16 * 20];
    __shared__ __align__(16) float aS[2][16 * 132];
    __shared__ __align__(16) float bS[64 * 36];
    __shared__ __align__(16) float cS[16 * 164];
    __shared__ __align__(16) float psArr[256];
    __shared__ float SinvBuf;

    const int tid = threadIdx.x;
    const int warp = tid >> 5, lane = tid & 31;

    // exp'd, padded transition matrices (A1, A2 in smem)
    {
        A1p[(tid >> 4) * 20 + (tid & 15)] = expf(logA1[tid]);
        A2p[(tid >> 4) * 20 + (tid & 15)] = expf(logA2[tid]);
    }

    // A3 fully register-resident: A3r[d3][j] = (A3[d3,2j], A3[d3,2j+1])
    unsigned long long A3r[8][4];
#pragma unroll
    for (int d3 = 0; d3 < 8; d3++)
#pragma unroll
        for (int j = 0; j < 4; j++)
            A3r[d3][j] = pk2(expf(logA3[d3 * 8 + 2 * j]),
                             expf(logA3[d3 * 8 + 2 * j + 1]));

    // ---- phase-2 ids: thread = (p1,p2) pair exactly
    const int p2p1 = tid >> 4, p2p2 = tid & 15;
    const int bwbase = ((p2p1 >> 1) * 8) * 36 + 16 * (p2p1 & 1) + p2p2;

    // ---- phase-3 ids: g3=(p1,d3), sub in {0,1}; outputs d2 = 2j+sub
    const int g3 = tid >> 1;
    const int p3p1 = g3 >> 3, p3d3 = g3 & 7, p3sub = tid & 1;
    const int brbase = ((p3p1 >> 1) * 8 + p3d3) * 36 + 16 * (p3p1 & 1);

    // ---- phase-4 ids: g4=(d2,d3), sub in {0,1}; outputs d1 = 2k+sub
    const int g4 = tid >> 1;
    const int p4d2 = g4 >> 3, p4d3 = g4 & 7, p4sub = tid & 1;
    const int em_b = p4sub * 128 + p4d2 * 8 + p4d3;   // + k*256 (global state idx)
    const int aw_b = p4sub * 132 + p4d2 * 8 + p4d3;   // + k*264 (smem aS idx)
    const int cvbase = p4d2 * 164 + p4d3 * 20;
    const int sxor = p4d2 & 3;

    double Lmx = 0.0, Lls = 0.0;
    float mx_reg = g_mx[0];
    float egC[8];

    __syncthreads();

    // ---- t = 0: w = em0 * pi  (phase-4 mapping); prefetch em for t=1
    {
        float ps = 0.f;
#pragma unroll
        for (int k = 0; k < 8; k++) {
            int ei = em_b + k * 256;
            float u = g_em[ei] * g_pi[ei];
            aS[0][aw_b + k * 264] = u;
            ps += u;
            egC[k] = g_em[SDIM + ei];   // emission for t=1
        }
        psArr[tid] = ps;
    }
    __syncthreads();

    for (int t = 1; t < T_MAX; t++) {
        const float* acur = &aS[(t - 1) & 1][0];
        float* anext = &aS[t & 1][0];

        // ---- warp0: reduce psArr -> S_{t-1}; overlaps phases 2-3 of the
        //      other warps (SinvBuf consumed only in phase 4).
        if (warp == 0) {
            const float4* pp = (const float4*)psArr;
            float4 v0 = pp[lane], v1 = pp[lane + 32];
            float r = (v0.x + v0.y) + (v0.z + v0.w)
                    + (v1.x + v1.y) + (v1.z + v1.w);
#pragma unroll
            for (int o = 16; o > 0; o >>= 1) r += __shfl_xor_sync(0xffffffffu, r, o);
            if (lane == 0) {
                SinvBuf = 1.0f / r;
                Lls += (double)logf(r);      // log S_{t-1}
                Lmx += (double)mx_reg;       // mx_{t-1}
                mx_reg = g_mx[t];
            }
        }

        // ---- phase 2: b[p1,p2,d3] = sum_p3 A3[d3,p3] * a[p1,p2,p3]  (A3 in regs)
        {
            const float* ap = acur + p2p1 * 132 + p2p2 * 8;
            ulonglong2 V0 = *(const ulonglong2*)ap;
            ulonglong2 V1 = *(const ulonglong2*)(ap + 4);
#pragma unroll
            for (int d3 = 0; d3 < 8; d3++) {
                unsigned long long acc = mul2(A3r[d3][0], V0.x);
                acc = fma2(A3r[d3][1], V0.y, acc);
                acc = fma2(A3r[d3][2], V1.x, acc);
                acc = fma2(A3r[d3][3], V1.y, acc);
                bS[bwbase + d3 * 36] = hadd2(acc);   // conflict-free stores
            }
        }
        __syncthreads();

        // ---- phase 3: c[p1,d2,d3] = sum_p2 A2[d2,p2] * b[p1,d3,p2]
        {
            const ulonglong2* bp = (const ulonglong2*)(bS + brbase);
            ulonglong2 B0 = bp[0], B1 = bp[1], B2 = bp[2], B3 = bp[3];
            const int cwp1 = p3p1 ^ (4 * sxor & 0);  // placeholder (unused)
            (void)cwp1;
#pragma unroll
            for (int j = 0; j < 8; j++) {
                int d2 = 2 * j + p3sub;
                const ulonglong2* w = (const ulonglong2*)(A2p + d2 * 20);
                ulonglong2 Wa = w[0], Wb = w[1], Wc = w[2], Wd = w[3];
                unsigned long long acc = mul2(Wa.x, B0.x);
                acc = fma2(Wa.y, B0.y, acc);
                acc = fma2(Wb.x, B1.x, acc);
                acc = fma2(Wb.y, B1.y, acc);
                acc = fma2(Wc.x, B2.x, acc);
                acc = fma2(Wc.y, B2.y, acc);
                acc = fma2(Wd.x, B3.x, acc);
                acc = fma2(Wd.y, B3.y, acc);
                // chunk-XOR swizzle on p1 by (d2&3)
                cS[d2 * 164 + p3d3 * 20 + (p3p1 ^ (4 * (d2 & 3)))] = hadd2(acc);
            }
        }
        __syncthreads();

        // ---- phase 4: w[d1,d2,d3] = em * (1/S_{t-1}) * sum_p1 A1[d1,p1]*c[p1,d2,d3]
        {
            const float* crow = cS + cvbase;
            ulonglong2 CV0 = *(const ulonglong2*)(crow + 4 * (0 ^ sxor));
            ulonglong2 CV1 = *(const ulonglong2*)(crow + 4 * (1 ^ sxor));
            ulonglong2 CV2 = *(const ulonglong2*)(crow + 4 * (2 ^ sxor));
            ulonglong2 CV3 = *(const ulonglong2*)(crow + 4 * (3 ^ sxor));
            float invS = SinvBuf;
            float ps = 0.f;
            const float* emn = g_em + (size_t)(t + 1 < T_MAX ? t + 1 : t) * SDIM + em_b;
#pragma unroll
            for (int k = 0; k < 8; k++) {
                int d1 = 2 * k + p4sub;
                const ulonglong2* w = (const ulonglong2*)(A1p + d1 * 20);
                ulonglong2 Wa = w[0], Wb = w[1], Wc = w[2], Wd = w[3];
                unsigned long long acc = mul2(Wa.x, CV0.x);
                acc = fma2(Wa.y, CV0.y, acc);
                acc = fma2(Wb.x, CV1.x, acc);
                acc = fma2(Wb.y, CV1.y, acc);
                acc = fma2(Wc.x, CV2.x, acc);
                acc = fma2(Wc.y, CV2.y, acc);
                acc = fma2(Wd.x, CV3.x, acc);
                acc = fma2(Wd.y, CV3.y, acc);
                float u = egC[k] * invS * hadd2(acc);
                anext[aw_b + k * 264] = u;
                ps += u;
                egC[k] = emn[k * 256];     // prefetch t+1 (full step of cover)
            }
            psArr[tid] = ps;
        }
        __syncthreads();
    }

    // ---- finalize: S_{T-1}
    if (warp == 0) {
        const float4* pp = (const float4*)psArr;
        float4 v0 = pp[lane], v1 = pp[lane + 32];
        float r = (v0.x + v0.y) + (v0.z + v0.w)
                + (v1.x + v1.y) + (v1.z + v1.w);
#pragma unroll
        for (int o = 16; o > 0; o >>= 1) r += __shfl_xor_sync(0xffffffffu, r, o);
        if (lane == 0) {
            double L = Lmx + Lls + (double)mx_reg + (double)logf(r);
            out[0] = (float)L;
        }
    }
}

// ============================================================
extern "C" void kernel_launch(void* const* d_in, const int* in_sizes, int n_in,
                              void* d_out, int out_size) {
    const int*   x      = (const int*)d_in[0];
    const float* lam1   = (const float*)d_in[1];
    const float* lam2   = (const float*)d_in[2];
    const float* lam3   = (const float*)d_in[3];
    const float* logA1  = (const float*)d_in[4];
    const float* logA2  = (const float*)d_in[5];
    const float* logA3  = (const float*)d_in[6];
    const float* logpi1 = (const float*)d_in[7];
    const float* logpi2 = (const float*)d_in[8];
    const float* logpi3 = (const float*)d_in[9];
    float* out = (float*)d_out;

    setup_kernel<<<8, 256>>>(lam1, lam2, lam3, logpi1, logpi2, logpi3);
    emis_kernel<<<T_MAX, 256>>>(x);
    scan_kernel<<<1, 256>>>(logA1, logA2, logA3, out);
}